// round 14
// baseline (speedup 1.0000x reference)
#include <cuda_runtime.h>
#include <cuda_fp16.h>
#include <cstdint>

// ---------------------------------------------------------------------------
// Problem constants
// ---------------------------------------------------------------------------
#define M_DIM 256
#define K_DIM 4096
#define N_DIM 11008
#define G_DIM 32
#define R_DIM 16
#define SCALING 2.0f

#define BM 64
#define BN 64
#define BK 32
#define KT2 (K_DIM / (2 * BK))   // 64 super-iters (64 k each)

// SMEM: 4 stages = 2 pairs. A [64][32] fp16 pitch 80 (5120 B), B same.
#define PITCH  80
#define A_ST   5120
#define NSTG   4
#define B_BASE (NSTG * A_ST)              // 20480
#define B_ST   5120
#define SMEM_BYTES (B_BASE + NSTG * B_ST) // 40960  -> 5 CTAs/SM
// LoRA tiles reuse stage-0 smem after the main loop:
#define SXA 0        // xa [64][16] fp16, pitch 32
#define SLB 2048     // lB [64][16] fp16, pitch 32

// Global scratch
__device__ __align__(16) float  g_xa[M_DIM * R_DIM];
__device__ __align__(16) __half g_x16[(size_t)M_DIM * K_DIM];   // x in fp16
__device__ __align__(16) __half g_w16[(size_t)N_DIM * K_DIM];   // (q-z)*s in fp16

// ---------------------------------------------------------------------------
// helpers (family-common PTX)
// ---------------------------------------------------------------------------
__device__ __forceinline__ uint32_t smem_u32(const void* p) {
    uint32_t a;
    asm("{ .reg .u64 t; cvta.to.shared.u64 t, %1; cvt.u32.u64 %0, t; }"
        : "=r"(a) : "l"(p));
    return a;
}
__device__ __forceinline__ void ldsm_x4(uint32_t addr, uint32_t* r) {
    asm volatile("ldmatrix.sync.aligned.m8n8.x4.shared.b16 {%0,%1,%2,%3}, [%4];"
                 : "=r"(r[0]), "=r"(r[1]), "=r"(r[2]), "=r"(r[3]) : "r"(addr));
}
__device__ __forceinline__ void ldsm_x2(uint32_t addr, uint32_t* r) {
    asm volatile("ldmatrix.sync.aligned.m8n8.x2.shared.b16 {%0,%1}, [%2];"
                 : "=r"(r[0]), "=r"(r[1]) : "r"(addr));
}
__device__ __forceinline__ void mma_f16(float* c, const uint32_t* a, const uint32_t* b) {
    asm volatile(
        "mma.sync.aligned.m16n8k16.row.col.f32.f16.f16.f32 "
        "{%0,%1,%2,%3}, {%4,%5,%6,%7}, {%8,%9}, {%0,%1,%2,%3};"
        : "+f"(c[0]), "+f"(c[1]), "+f"(c[2]), "+f"(c[3])
        : "r"(a[0]), "r"(a[1]), "r"(a[2]), "r"(a[3]), "r"(b[0]), "r"(b[1]));
}
__device__ __forceinline__ void cpa16(uint32_t dst, const void* src) {
    asm volatile("cp.async.cg.shared.global [%0], [%1], 16;"
                 :: "r"(dst), "l"(src) : "memory");
}
__device__ __forceinline__ void cpa_commit() {
    asm volatile("cp.async.commit_group;" ::: "memory");
}
__device__ __forceinline__ void cpa_wait0() {
    asm volatile("cp.async.wait_group 0;" ::: "memory");
}
__device__ __forceinline__ uint32_t pack_f16(float v0, float v1) {
    __half2 p = __floats2half2_rn(v0, v1);
    return *reinterpret_cast<uint32_t*>(&p);
}

// ---------------------------------------------------------------------------
// Kernel 0: fused x-prep (fp16 conversion + lora_A reduction)
// ---------------------------------------------------------------------------
__global__ __launch_bounds__(256)
void xprep_kernel(const float* __restrict__ x, const float* __restrict__ loraA) {
    const int m   = blockIdx.x;
    const int tid = threadIdx.x;
    const int lid = tid & 31;
    const int wid = tid >> 5;

    float acc[R_DIM];
#pragma unroll
    for (int r = 0; r < R_DIM; r++) acc[r] = 0.f;

    const float4* x4 = reinterpret_cast<const float4*>(x + (size_t)m * K_DIM);
    const float4* a4 = reinterpret_cast<const float4*>(loraA);
    uint2* xo = reinterpret_cast<uint2*>(g_x16 + (size_t)m * K_DIM);

#pragma unroll
    for (int i = 0; i < 4; i++) {
        const int f = tid + i * 256;
        float4 xv = x4[f];
        xo[f] = make_uint2(pack_f16(xv.x, xv.y), pack_f16(xv.z, xv.w));
#pragma unroll
        for (int r = 0; r < R_DIM; r++) {
            float4 av = a4[r * (K_DIM / 4) + f];
            acc[r] = fmaf(xv.x, av.x, acc[r]);
            acc[r] = fmaf(xv.y, av.y, acc[r]);
            acc[r] = fmaf(xv.z, av.z, acc[r]);
            acc[r] = fmaf(xv.w, av.w, acc[r]);
        }
    }
#pragma unroll
    for (int r = 0; r < R_DIM; r++) {
#pragma unroll
        for (int o = 16; o > 0; o >>= 1)
            acc[r] += __shfl_xor_sync(0xFFFFFFFFu, acc[r], o);
    }
    __shared__ float red[8][R_DIM];
    if (lid == 0) {
#pragma unroll
        for (int r = 0; r < R_DIM; r++) red[wid][r] = acc[r];
    }
    __syncthreads();
    if (tid < R_DIM) {
        float v = 0.f;
#pragma unroll
        for (int w = 0; w < 8; w++) v += red[w][tid];
        g_xa[m * R_DIM + tid] = v * SCALING;
    }
}

// ---------------------------------------------------------------------------
// Kernel 0b: w16 = (qweight - zeros) * scales in fp16; 16 elems/thread
// ---------------------------------------------------------------------------
__global__ __launch_bounds__(256)
void pack_w16(const int* __restrict__ qw, const int* __restrict__ zeros,
              const float* __restrict__ scales) {
    const size_t base = ((size_t)blockIdx.x * 256 + threadIdx.x) * 16;
    const int o = (int)(base >> 12);
    const int i = (int)(base & 4095);
    const int g = o * G_DIM + (i >> 7);
    const float z = (float)zeros[g];
    const float s = scales[g];
    const float nz = -z * s;

    int4 a = reinterpret_cast<const int4*>(qw + base)[0];
    int4 b = reinterpret_cast<const int4*>(qw + base)[1];
    int4 c = reinterpret_cast<const int4*>(qw + base)[2];
    int4 d = reinterpret_cast<const int4*>(qw + base)[3];

    uint4 w0, w1;
    w0.x = pack_f16(fmaf((float)a.x, s, nz), fmaf((float)a.y, s, nz));
    w0.y = pack_f16(fmaf((float)a.z, s, nz), fmaf((float)a.w, s, nz));
    w0.z = pack_f16(fmaf((float)b.x, s, nz), fmaf((float)b.y, s, nz));
    w0.w = pack_f16(fmaf((float)b.z, s, nz), fmaf((float)b.w, s, nz));
    w1.x = pack_f16(fmaf((float)c.x, s, nz), fmaf((float)c.y, s, nz));
    w1.y = pack_f16(fmaf((float)c.z, s, nz), fmaf((float)c.w, s, nz));
    w1.z = pack_f16(fmaf((float)d.x, s, nz), fmaf((float)d.y, s, nz));
    w1.w = pack_f16(fmaf((float)d.z, s, nz), fmaf((float)d.w, s, nz));

    reinterpret_cast<uint4*>(g_w16 + base)[0] = w0;
    reinterpret_cast<uint4*>(g_w16 + base)[1] = w1;
}

// ---------------------------------------------------------------------------
// Kernel 2: main GEMM — R10 geometry, pair-double-buffered pipeline.
// CTA 64x64, 128 threads, 4 warps (2m x 2n, 32x32 each), 5 CTAs/SM.
// Per super-iter (64 k): prefetch other pair, compute this pair (4 k16,
// frag-double-buffered), ONE wait + ONE barrier. 64 barriers total.
// ---------------------------------------------------------------------------
__global__ __launch_bounds__(128, 5)
void gptq_lora_mma(const float* __restrict__ loraB,
                   float*       __restrict__ out) {
    extern __shared__ __align__(16) char sm[];
    const uint32_t sb = smem_u32(sm);

    const int tid  = threadIdx.x;
    const int lane = tid & 31;
    const int wid  = tid >> 5;
    const int m0   = blockIdx.x * BM;    // 4 m-tiles (fastest -> w16 L2 dedup)
    const int n0   = blockIdx.y * BN;    // 172 n-tiles

    // ---- loader mappings: 64 rows x 64B per stage; 2 threads/row, 32B each ----
    const int lrow = tid >> 1;
    const int lhal = (tid & 1) * 32;                 // byte offset in row
    const __half* ag = g_x16 + (size_t)(m0 + lrow) * K_DIM + (lhal >> 1);
    const __half* bg = g_w16 + (size_t)(n0 + lrow) * K_DIM + (lhal >> 1);
    const uint32_t l_soff = (uint32_t)(lrow * PITCH + lhal);

    // pair p occupies stages {2p, 2p+1}; kt-pair j covers k = j*64 .. j*64+63
    // (stage 2p -> first 32 k, stage 2p+1 -> second 32 k)

    // ---- prologue: load pair 0 (kt-pair 0), wait, sync ----
    {
        const uint32_t A0 = sb + 0 * A_ST, A1 = sb + 1 * A_ST;
        const uint32_t B0 = sb + B_BASE + 0 * B_ST, B1 = sb + B_BASE + 1 * B_ST;
        cpa16(A0 + l_soff,      ag);
        cpa16(A0 + l_soff + 16, ag + 8);
        cpa16(A1 + l_soff,      ag + 32);
        cpa16(A1 + l_soff + 16, ag + 40);
        cpa16(B0 + l_soff,      bg);
        cpa16(B0 + l_soff + 16, bg + 8);
        cpa16(B1 + l_soff,      bg + 32);
        cpa16(B1 + l_soff + 16, bg + 40);
        cpa_commit();
    }

    // ---- accumulators / compute mappings ----
    float tac[2][4][4];
#pragma unroll
    for (int mi = 0; mi < 2; mi++)
#pragma unroll
        for (int ni = 0; ni < 4; ni++)
#pragma unroll
            for (int j = 0; j < 4; j++) tac[mi][ni][j] = 0.f;

    const int wm = (wid >> 1) * 32;            // 0/32
    const int wn = (wid & 1) * 32;             // 0/32
    const uint32_t aoff  = (uint32_t)((wm + (lane & 15)) * PITCH + ((lane >> 4) << 4));
    const uint32_t boff4 = (uint32_t)((wn + (lane & 7) + ((lane >> 4) << 3)) * PITCH
                                      + (((lane >> 3) & 1) << 4));

    cpa_wait0();          // pair 0 complete (own copies)
    __syncthreads();      // fully visible

    // frag double buffers
    uint32_t fa[2][2][4], fb[2][4][2];

    for (int j = 0; j < KT2; j++) {
        const int c = j & 1;                 // compute pair
        const int p = c ^ 1;                 // prefetch pair (holds kt-pair j+1)

        // 1. prefetch pair p <- kt-pair j+1 (pair p finished at iter j-1; barrier passed)
        if (j < KT2 - 1) {
            const int ke = (j + 1) * 64;     // k offset (elements)
            const uint32_t Ap0 = sb + (uint32_t)((2 * p) * A_ST);
            const uint32_t Ap1 = sb + (uint32_t)((2 * p + 1) * A_ST);
            const uint32_t Bp0 = sb + B_BASE + (uint32_t)((2 * p) * B_ST);
            const uint32_t Bp1 = sb + B_BASE + (uint32_t)((2 * p + 1) * B_ST);
            cpa16(Ap0 + l_soff,      ag + ke);
            cpa16(Ap0 + l_soff + 16, ag + ke + 8);
            cpa16(Ap1 + l_soff,      ag + ke + 32);
            cpa16(Ap1 + l_soff + 16, ag + ke + 40);
            cpa16(Bp0 + l_soff,      bg + ke);
            cpa16(Bp0 + l_soff + 16, bg + ke + 8);
            cpa16(Bp1 + l_soff,      bg + ke + 32);
            cpa16(Bp1 + l_soff + 16, bg + ke + 40);
        }
        cpa_commit();

        // 2. compute pair c: 4 k16 chunks, frag-double-buffered
        {
            const uint32_t Ab[2] = { sb + (uint32_t)((2 * c) * A_ST) + aoff,
                                     sb + (uint32_t)((2 * c + 1) * A_ST) + aoff };
            const uint32_t Bb[2] = { sb + B_BASE + (uint32_t)((2 * c) * B_ST) + boff4,
                                     sb + B_BASE + (uint32_t)((2 * c + 1) * B_ST) + boff4 };

            // preload chunk 0 into buffer 0
#pragma unroll
            for (int mi = 0; mi < 2; mi++)
                ldsm_x4(Ab[0] + mi * (16 * PITCH), fa[0][mi]);
#pragma unroll
            for (int nj = 0; nj < 2; nj++) {
                uint32_t t[4];
                ldsm_x4(Bb[0] + nj * (16 * PITCH), t);
                fb[0][2 * nj][0] = t[0]; fb[0][2 * nj][1] = t[1];
                fb[0][2 * nj + 1][0] = t[2]; fb[0][2 * nj + 1][1] = t[3];
            }
#pragma unroll
            for (int kk = 0; kk < 4; kk++) {
                const int cur = kk & 1, nxt = cur ^ 1;
                if (kk < 3) {
                    const int ci = kk + 1;                    // next chunk
                    const uint32_t Abn = Ab[ci >> 1] + (uint32_t)((ci & 1) * 32);
                    const uint32_t Bbn = Bb[ci >> 1] + (uint32_t)((ci & 1) * 32);
#pragma unroll
                    for (int mi = 0; mi < 2; mi++)
                        ldsm_x4(Abn + mi * (16 * PITCH), fa[nxt][mi]);
#pragma unroll
                    for (int nj = 0; nj < 2; nj++) {
                        uint32_t t[4];
                        ldsm_x4(Bbn + nj * (16 * PITCH), t);
                        fb[nxt][2 * nj][0] = t[0]; fb[nxt][2 * nj][1] = t[1];
                        fb[nxt][2 * nj + 1][0] = t[2]; fb[nxt][2 * nj + 1][1] = t[3];
                    }
                }
#pragma unroll
                for (int mi = 0; mi < 2; mi++)
#pragma unroll
                    for (int ni = 0; ni < 4; ni++)
                        mma_f16(tac[mi][ni], fa[cur][mi], fb[cur][ni]);
            }
        }

        // 3. pair p's copies (issued ~4k cycles ago) complete; publish
        cpa_wait0();
        __syncthreads();
    }

    // ---- LoRA tiles: reuse stage-0 smem (all compute done) ----
    {
        const int row = tid & 63;
        const float* src = (tid < 64)
            ? (g_xa + (size_t)(m0 + row) * R_DIM)
            : (loraB + (size_t)(n0 + row) * R_DIM);
        char* dst = sm + ((tid < 64) ? SXA : SLB) + row * 32;
        float4 v0 = reinterpret_cast<const float4*>(src)[0];
        float4 v1 = reinterpret_cast<const float4*>(src)[1];
        float4 v2 = reinterpret_cast<const float4*>(src)[2];
        float4 v3 = reinterpret_cast<const float4*>(src)[3];
        *reinterpret_cast<uint4*>(dst) =
            make_uint4(pack_f16(v0.x, v0.y), pack_f16(v0.z, v0.w),
                       pack_f16(v1.x, v1.y), pack_f16(v1.z, v1.w));
        *reinterpret_cast<uint4*>(dst + 16) =
            make_uint4(pack_f16(v2.x, v2.y), pack_f16(v2.z, v2.w),
                       pack_f16(v3.x, v3.y), pack_f16(v3.z, v3.w));
    }
    __syncthreads();

    // ---- LoRA k16 step ----
    {
        uint32_t ah[2][4], b[4][2];
#pragma unroll
        for (int mi = 0; mi < 2; mi++)
            ldsm_x4(sb + SXA + (uint32_t)((wm + mi * 16 + (lane & 15)) * 32
                                          + ((lane >> 4) << 4)), ah[mi]);
#pragma unroll
        for (int ni = 0; ni < 4; ni++)
            ldsm_x2(sb + SLB + (uint32_t)((wn + ni * 8 + (lane & 7)) * 32
                                          + (((lane >> 3) & 1) << 4)), b[ni]);
#pragma unroll
        for (int mi = 0; mi < 2; mi++)
#pragma unroll
            for (int ni = 0; ni < 4; ni++)
                mma_f16(tac[mi][ni], ah[mi], b[ni]);
    }

    // ---- store ----
    {
        const int r  = lane >> 2;
        const int c2 = (lane & 3) * 2;
#pragma unroll
        for (int mi = 0; mi < 2; mi++) {
#pragma unroll
            for (int ni = 0; ni < 4; ni++) {
                const int m = m0 + wm + mi * 16 + r;
                const int n = n0 + wn + ni * 8 + c2;
                float* p = out + (size_t)m * N_DIM + n;
                *reinterpret_cast<float2*>(p) =
                    make_float2(tac[mi][ni][0], tac[mi][ni][1]);
                *reinterpret_cast<float2*>(p + 8 * (size_t)N_DIM) =
                    make_float2(tac[mi][ni][2], tac[mi][ni][3]);
            }
        }
    }
}

// ---------------------------------------------------------------------------
// kernel_launch — inputs: x, qweight, scales, zeros, lora_A, lora_B
// ---------------------------------------------------------------------------
extern "C" void kernel_launch(void* const* d_in, const int* in_sizes, int n_in,
                              void* d_out, int out_size) {
    const float* x      = (const float*)d_in[0];
    const int*   qw     = (const int*)  d_in[1];
    const float* scales = (const float*)d_in[2];
    const int*   zeros  = (const int*)  d_in[3];
    const float* loraA  = (const float*)d_in[4];
    const float* loraB  = (const float*)d_in[5];
    float*       out    = (float*)d_out;

    cudaFuncSetAttribute(gptq_lora_mma,
                         cudaFuncAttributeMaxDynamicSharedMemorySize, SMEM_BYTES);

    xprep_kernel<<<M_DIM, 256>>>(x, loraA);
    pack_w16<<<(int)(((size_t)N_DIM * K_DIM) / (256 * 16)), 256>>>(qw, zeros, scales);

    dim3 grid(M_DIM / BM, N_DIM / BN);   // (4, 172): m fastest -> w16 L2 dedup
    gptq_lora_mma<<<grid, 128, SMEM_BYTES>>>(loraB, out);
}

// round 15
// speedup vs baseline: 1.0792x; 1.0792x over previous
#include <cuda_runtime.h>
#include <cuda_fp16.h>
#include <cstdint>

// ---------------------------------------------------------------------------
// Problem constants
// ---------------------------------------------------------------------------
#define M_DIM 256
#define K_DIM 4096
#define N_DIM 11008
#define G_DIM 32
#define R_DIM 16
#define SCALING 2.0f

#define BM 64
#define BN 64
#define BK 32
#define KT (K_DIM / BK)     // 128

// SMEM: 4 stages. A [64][32] fp16 pitch 80 (5120 B), B [64][32] fp16 pitch 80.
#define PITCH  80
#define A_ST   5120
#define NSTG   4
#define B_BASE (NSTG * A_ST)              // 20480
#define B_ST   5120
#define SMEM_BYTES (B_BASE + NSTG * B_ST) // 40960  -> 5 CTAs/SM
// LoRA tiles reuse stage-0 smem after the main loop:
#define SXA 0        // xa [64][16] fp16, pitch 32
#define SLB 2048     // lB [64][16] fp16, pitch 32

// Prep grid split
#define XPREP_BLOCKS 256
#define PACK_BLOCKS  ((int)(((size_t)N_DIM * K_DIM) / (256 * 16)))   // 11008

// Global scratch
__device__ __align__(16) float  g_xa[M_DIM * R_DIM];
__device__ __align__(16) __half g_x16[(size_t)M_DIM * K_DIM];   // x in fp16
__device__ __align__(16) __half g_w16[(size_t)N_DIM * K_DIM];   // (q-z)*s in fp16

// ---------------------------------------------------------------------------
// helpers (family-common PTX)
// ---------------------------------------------------------------------------
__device__ __forceinline__ uint32_t smem_u32(const void* p) {
    uint32_t a;
    asm("{ .reg .u64 t; cvta.to.shared.u64 t, %1; cvt.u32.u64 %0, t; }"
        : "=r"(a) : "l"(p));
    return a;
}
__device__ __forceinline__ void ldsm_x4(uint32_t addr, uint32_t* r) {
    asm volatile("ldmatrix.sync.aligned.m8n8.x4.shared.b16 {%0,%1,%2,%3}, [%4];"
                 : "=r"(r[0]), "=r"(r[1]), "=r"(r[2]), "=r"(r[3]) : "r"(addr));
}
__device__ __forceinline__ void ldsm_x2(uint32_t addr, uint32_t* r) {
    asm volatile("ldmatrix.sync.aligned.m8n8.x2.shared.b16 {%0,%1}, [%2];"
                 : "=r"(r[0]), "=r"(r[1]) : "r"(addr));
}
__device__ __forceinline__ void mma_f16(float* c, const uint32_t* a, const uint32_t* b) {
    asm volatile(
        "mma.sync.aligned.m16n8k16.row.col.f32.f16.f16.f32 "
        "{%0,%1,%2,%3}, {%4,%5,%6,%7}, {%8,%9}, {%0,%1,%2,%3};"
        : "+f"(c[0]), "+f"(c[1]), "+f"(c[2]), "+f"(c[3])
        : "r"(a[0]), "r"(a[1]), "r"(a[2]), "r"(a[3]), "r"(b[0]), "r"(b[1]));
}
__device__ __forceinline__ void cpa16(uint32_t dst, const void* src) {
    asm volatile("cp.async.cg.shared.global [%0], [%1], 16;"
                 :: "r"(dst), "l"(src) : "memory");
}
__device__ __forceinline__ void cpa_commit() {
    asm volatile("cp.async.commit_group;" ::: "memory");
}
__device__ __forceinline__ void cpa_wait2() {
    asm volatile("cp.async.wait_group 2;" ::: "memory");
}
__device__ __forceinline__ uint32_t pack_f16(float v0, float v1) {
    __half2 p = __floats2half2_rn(v0, v1);
    return *reinterpret_cast<uint32_t*>(&p);
}

// ---------------------------------------------------------------------------
// Kernel 0 (fused prep, one launch):
//   blocks [0, 256):    xprep — g_x16 row conversion + xa reduction
//   blocks [256, 11264): pack  — w16 = (q - z) * s, 16 elems/thread
// The two halves are independent; fusing them overlaps xprep's
// latency-bound blocks with pack's DRAM-bound waves.
// ---------------------------------------------------------------------------
__global__ __launch_bounds__(256)
void prep_kernel(const float* __restrict__ x,  const float* __restrict__ loraA,
                 const int* __restrict__ qw,   const int* __restrict__ zeros,
                 const float* __restrict__ scales) {
    const int tid = threadIdx.x;

    if (blockIdx.x < XPREP_BLOCKS) {
        // ---------------- xprep ----------------
        const int m   = blockIdx.x;
        const int lid = tid & 31;
        const int wid = tid >> 5;

        float acc[R_DIM];
#pragma unroll
        for (int r = 0; r < R_DIM; r++) acc[r] = 0.f;

        const float4* x4 = reinterpret_cast<const float4*>(x + (size_t)m * K_DIM);
        const float4* a4 = reinterpret_cast<const float4*>(loraA);
        uint2* xo = reinterpret_cast<uint2*>(g_x16 + (size_t)m * K_DIM);

#pragma unroll
        for (int i = 0; i < 4; i++) {
            const int f = tid + i * 256;
            float4 xv = x4[f];
            xo[f] = make_uint2(pack_f16(xv.x, xv.y), pack_f16(xv.z, xv.w));
#pragma unroll
            for (int r = 0; r < R_DIM; r++) {
                float4 av = a4[r * (K_DIM / 4) + f];
                acc[r] = fmaf(xv.x, av.x, acc[r]);
                acc[r] = fmaf(xv.y, av.y, acc[r]);
                acc[r] = fmaf(xv.z, av.z, acc[r]);
                acc[r] = fmaf(xv.w, av.w, acc[r]);
            }
        }
#pragma unroll
        for (int r = 0; r < R_DIM; r++) {
#pragma unroll
            for (int o = 16; o > 0; o >>= 1)
                acc[r] += __shfl_xor_sync(0xFFFFFFFFu, acc[r], o);
        }
        __shared__ float red[8][R_DIM];
        if (lid == 0) {
#pragma unroll
            for (int r = 0; r < R_DIM; r++) red[wid][r] = acc[r];
        }
        __syncthreads();
        if (tid < R_DIM) {
            float v = 0.f;
#pragma unroll
            for (int w = 0; w < 8; w++) v += red[w][tid];
            g_xa[m * R_DIM + tid] = v * SCALING;
        }
    } else {
        // ---------------- pack_w16 ----------------
        const size_t base =
            ((size_t)(blockIdx.x - XPREP_BLOCKS) * 256 + tid) * 16;
        const int o = (int)(base >> 12);
        const int i = (int)(base & 4095);
        const int g = o * G_DIM + (i >> 7);
        const float z = (float)zeros[g];
        const float s = scales[g];
        const float nz = -z * s;

        int4 a = reinterpret_cast<const int4*>(qw + base)[0];
        int4 b = reinterpret_cast<const int4*>(qw + base)[1];
        int4 c = reinterpret_cast<const int4*>(qw + base)[2];
        int4 d = reinterpret_cast<const int4*>(qw + base)[3];

        uint4 w0, w1;
        w0.x = pack_f16(fmaf((float)a.x, s, nz), fmaf((float)a.y, s, nz));
        w0.y = pack_f16(fmaf((float)a.z, s, nz), fmaf((float)a.w, s, nz));
        w0.z = pack_f16(fmaf((float)b.x, s, nz), fmaf((float)b.y, s, nz));
        w0.w = pack_f16(fmaf((float)b.z, s, nz), fmaf((float)b.w, s, nz));
        w1.x = pack_f16(fmaf((float)c.x, s, nz), fmaf((float)c.y, s, nz));
        w1.y = pack_f16(fmaf((float)c.z, s, nz), fmaf((float)c.w, s, nz));
        w1.z = pack_f16(fmaf((float)d.x, s, nz), fmaf((float)d.y, s, nz));
        w1.w = pack_f16(fmaf((float)d.z, s, nz), fmaf((float)d.w, s, nz));

        reinterpret_cast<uint4*>(g_w16 + base)[0] = w0;
        reinterpret_cast<uint4*>(g_w16 + base)[1] = w1;
    }
}

// ---------------------------------------------------------------------------
// Kernel 2: main GEMM — exact R13/R10 configuration (validated 120.6us).
// CTA 64x64, 128 threads, 4 warps (2m x 2n, 32x32 each), BK=32,
// 4-stage cp.async ring, distance-3 prefetch (wait_group 2), 5 CTAs/SM.
// Scales pre-folded; tac accumulates f32 directly; LoRA k16 epilogue.
// ---------------------------------------------------------------------------
__global__ __launch_bounds__(128, 5)
void gptq_lora_mma(const float* __restrict__ loraB,
                   float*       __restrict__ out) {
    extern __shared__ __align__(16) char sm[];
    const uint32_t sb = smem_u32(sm);

    const int tid  = threadIdx.x;
    const int lane = tid & 31;
    const int wid  = tid >> 5;
    const int m0   = blockIdx.x * BM;    // 4 m-tiles (fastest -> w16 L2 dedup)
    const int n0   = blockIdx.y * BN;    // 172 n-tiles

    // ---- loader mappings: 64 rows x 64B per tile; 2 threads/row, 32B each ----
    const int lrow = tid >> 1;
    const int lhal = (tid & 1) * 32;                 // byte offset in row
    const __half* ag = g_x16 + (size_t)(m0 + lrow) * K_DIM + (lhal >> 1);
    const __half* bg = g_w16 + (size_t)(n0 + lrow) * K_DIM + (lhal >> 1);
    const uint32_t l_soff = (uint32_t)(lrow * PITCH + lhal);

    // ---- prologue: stages 0..2 ----
#pragma unroll
    for (int s = 0; s < 3; s++) {
        const uint32_t As = sb + s * A_ST;
        const uint32_t Bs = sb + B_BASE + s * B_ST;
        cpa16(As + l_soff,      ag + s * BK);
        cpa16(As + l_soff + 16, ag + s * BK + 8);
        cpa16(Bs + l_soff,      bg + s * BK);
        cpa16(Bs + l_soff + 16, bg + s * BK + 8);
        cpa_commit();
    }

    // ---- accumulators / compute mappings ----
    float tac[2][4][4];
#pragma unroll
    for (int mi = 0; mi < 2; mi++)
#pragma unroll
        for (int ni = 0; ni < 4; ni++)
#pragma unroll
            for (int j = 0; j < 4; j++) tac[mi][ni][j] = 0.f;

    const int wm = (wid >> 1) * 32;            // 0/32
    const int wn = (wid & 1) * 32;             // 0/32
    const uint32_t aoff  = (uint32_t)((wm + (lane & 15)) * PITCH + ((lane >> 4) << 4));
    const uint32_t boff4 = (uint32_t)((wn + (lane & 7) + ((lane >> 4) << 3)) * PITCH
                                      + (((lane >> 3) & 1) << 4));

    cpa_wait2();          // stage 0 complete (own groups)
    __syncthreads();      // all threads' -> fully visible

    // frag double buffers
    uint32_t fa[2][2][4], fb[2][4][2];

    for (int kt = 0; kt < KT; kt++) {
        // 1. prefetch stage kt+3
        if (kt < KT - 3) {
            const int ks = kt + 3;
            const int st = ks & 3;
            const uint32_t As = sb + st * A_ST;
            const uint32_t Bs = sb + B_BASE + st * B_ST;
            cpa16(As + l_soff,      ag + ks * BK);
            cpa16(As + l_soff + 16, ag + ks * BK + 8);
            cpa16(Bs + l_soff,      bg + ks * BK);
            cpa16(Bs + l_soff + 16, bg + ks * BK + 8);
        }
        cpa_commit();

        // 2. compute stage kt&3: 2 x k16 HMMA, frag-double-buffered
        {
            const uint32_t Ab = sb + (uint32_t)((kt & 3) * A_ST) + aoff;
            const uint32_t Bb = sb + B_BASE + (uint32_t)((kt & 3) * B_ST) + boff4;

            // load kk=0 into buffer 0
#pragma unroll
            for (int mi = 0; mi < 2; mi++)
                ldsm_x4(Ab + mi * (16 * PITCH), fa[0][mi]);
#pragma unroll
            for (int nj = 0; nj < 2; nj++) {
                uint32_t t[4];
                ldsm_x4(Bb + nj * (16 * PITCH), t);
                fb[0][2 * nj][0] = t[0]; fb[0][2 * nj][1] = t[1];
                fb[0][2 * nj + 1][0] = t[2]; fb[0][2 * nj + 1][1] = t[3];
            }
#pragma unroll
            for (int kk = 0; kk < 2; kk++) {
                const int cur = kk & 1, nxt = cur ^ 1;
                if (kk < 1) {
                    const uint32_t kb = 32;   // second k16 half (16 fp16 = 32B)
#pragma unroll
                    for (int mi = 0; mi < 2; mi++)
                        ldsm_x4(Ab + mi * (16 * PITCH) + kb, fa[nxt][mi]);
#pragma unroll
                    for (int nj = 0; nj < 2; nj++) {
                        uint32_t t[4];
                        ldsm_x4(Bb + nj * (16 * PITCH) + kb, t);
                        fb[nxt][2 * nj][0] = t[0]; fb[nxt][2 * nj][1] = t[1];
                        fb[nxt][2 * nj + 1][0] = t[2]; fb[nxt][2 * nj + 1][1] = t[3];
                    }
                }
#pragma unroll
                for (int mi = 0; mi < 2; mi++)
#pragma unroll
                    for (int ni = 0; ni < 4; ni++)
                        mma_f16(tac[mi][ni], fa[cur][mi], fb[cur][ni]);
            }
        }

        // 3. stage kt+1 complete; publish
        cpa_wait2();
        __syncthreads();
    }

    // ---- LoRA tiles: reuse stage-0 smem (all compute done) ----
    {
        const int row = tid & 63;
        const float* src = (tid < 64)
            ? (g_xa + (size_t)(m0 + row) * R_DIM)
            : (loraB + (size_t)(n0 + row) * R_DIM);
        char* dst = sm + ((tid < 64) ? SXA : SLB) + row * 32;
        float4 v0 = reinterpret_cast<const float4*>(src)[0];
        float4 v1 = reinterpret_cast<const float4*>(src)[1];
        float4 v2 = reinterpret_cast<const float4*>(src)[2];
        float4 v3 = reinterpret_cast<const float4*>(src)[3];
        *reinterpret_cast<uint4*>(dst) =
            make_uint4(pack_f16(v0.x, v0.y), pack_f16(v0.z, v0.w),
                       pack_f16(v1.x, v1.y), pack_f16(v1.z, v1.w));
        *reinterpret_cast<uint4*>(dst + 16) =
            make_uint4(pack_f16(v2.x, v2.y), pack_f16(v2.z, v2.w),
                       pack_f16(v3.x, v3.y), pack_f16(v3.z, v3.w));
    }
    __syncthreads();

    // ---- LoRA k16 step ----
    {
        uint32_t ah[2][4], b[4][2];
#pragma unroll
        for (int mi = 0; mi < 2; mi++)
            ldsm_x4(sb + SXA + (uint32_t)((wm + mi * 16 + (lane & 15)) * 32
                                          + ((lane >> 4) << 4)), ah[mi]);
#pragma unroll
        for (int ni = 0; ni < 4; ni++)
            ldsm_x2(sb + SLB + (uint32_t)((wn + ni * 8 + (lane & 7)) * 32
                                          + (((lane >> 3) & 1) << 4)), b[ni]);
#pragma unroll
        for (int mi = 0; mi < 2; mi++)
#pragma unroll
            for (int ni = 0; ni < 4; ni++)
                mma_f16(tac[mi][ni], ah[mi], b[ni]);
    }

    // ---- store ----
    {
        const int r  = lane >> 2;
        const int c2 = (lane & 3) * 2;
#pragma unroll
        for (int mi = 0; mi < 2; mi++) {
#pragma unroll
            for (int ni = 0; ni < 4; ni++) {
                const int m = m0 + wm + mi * 16 + r;
                const int n = n0 + wn + ni * 8 + c2;
                float* p = out + (size_t)m * N_DIM + n;
                *reinterpret_cast<float2*>(p) =
                    make_float2(tac[mi][ni][0], tac[mi][ni][1]);
                *reinterpret_cast<float2*>(p + 8 * (size_t)N_DIM) =
                    make_float2(tac[mi][ni][2], tac[mi][ni][3]);
            }
        }
    }
}

// ---------------------------------------------------------------------------
// kernel_launch — inputs: x, qweight, scales, zeros, lora_A, lora_B
// ---------------------------------------------------------------------------
extern "C" void kernel_launch(void* const* d_in, const int* in_sizes, int n_in,
                              void* d_out, int out_size) {
    const float* x      = (const float*)d_in[0];
    const int*   qw     = (const int*)  d_in[1];
    const float* scales = (const float*)d_in[2];
    const int*   zeros  = (const int*)  d_in[3];
    const float* loraA  = (const float*)d_in[4];
    const float* loraB  = (const float*)d_in[5];
    float*       out    = (float*)d_out;

    cudaFuncSetAttribute(gptq_lora_mma,
                         cudaFuncAttributeMaxDynamicSharedMemorySize, SMEM_BYTES);

    prep_kernel<<<XPREP_BLOCKS + PACK_BLOCKS, 256>>>(x, loraA, qw, zeros, scales);

    dim3 grid(M_DIM / BM, N_DIM / BN);   // (4, 172): m fastest -> w16 L2 dedup
    gptq_lora_mma<<<grid, 128, SMEM_BYTES>>>(loraB, out);
}